// round 1
// baseline (speedup 1.0000x reference)
#include <cuda_runtime.h>
#include <cstdint>

#define BATCH_MAX 16384
#define SEQ_L 50
#define DIM 100
#define FFDIM 2048
#define KPRED 100
#define EPS 1e-5f

// ---------------- scratch (device globals; no allocation allowed) ----------
__device__ float g_x [BATCH_MAX * DIM];                 // embedding sums
__device__ float g_x1[BATCH_MAX * DIM];                 // after attn + LN1
__device__ float g_h [(size_t)BATCH_MAX * FFDIM];       // FFN hidden (128 MB)
__device__ float g_ff[BATCH_MAX * DIM];                 // FFN output
__device__ float g_M [DIM * DIM];                       // Wo @ Wv collapsed
__device__ float g_c [DIM];                             // Wo @ bv + bo

// ---------------- K0: collapse attention to one matrix ---------------------
__global__ void precompute_attn(const float* __restrict__ in_proj_w,
                                const float* __restrict__ in_proj_b,
                                const float* __restrict__ out_proj_w,
                                const float* __restrict__ out_proj_b) {
    int i = blockIdx.x;          // output row
    int j = threadIdx.x;
    const float* Wv = in_proj_w + 2 * DIM * DIM;   // rows 2D..3D of in_proj_w
    const float* bv = in_proj_b + 2 * DIM;
    if (j < DIM) {
        float s = 0.f;
        #pragma unroll 4
        for (int k = 0; k < DIM; k++)
            s += out_proj_w[i * DIM + k] * Wv[k * DIM + j];
        g_M[i * DIM + j] = s;
    }
    if (j == 0) {
        float s = out_proj_b[i];
        for (int k = 0; k < DIM; k++)
            s += out_proj_w[i * DIM + k] * bv[k];
        g_c[i] = s;
    }
}

// ---------------- K1: embedding gather-sum ---------------------------------
__global__ void embed_sum(const int* __restrict__ seq,
                          const float* __restrict__ emb) {
    int b = blockIdx.x;
    __shared__ int s_idx[SEQ_L];
    int t = threadIdx.x;
    if (t < SEQ_L) s_idx[t] = seq[b * SEQ_L + t];
    __syncthreads();
    if (t < DIM) {
        float acc = 0.f;
        #pragma unroll 5
        for (int l = 0; l < SEQ_L; l++)
            acc += emb[(size_t)s_idx[l] * DIM + t];
        g_x[b * DIM + t] = acc;
    }
}

// ---------------- block reduce (sum, sumsq) over 128 threads ---------------
__device__ __forceinline__ void block_reduce2(float& a, float& b, float* sred) {
    #pragma unroll
    for (int off = 16; off; off >>= 1) {
        a += __shfl_down_sync(0xffffffffu, a, off);
        b += __shfl_down_sync(0xffffffffu, b, off);
    }
    int w = threadIdx.x >> 5, lane = threadIdx.x & 31;
    if (lane == 0) { sred[w] = a; sred[w + 4] = b; }
    __syncthreads();
    if (threadIdx.x == 0) {
        sred[0] = sred[0] + sred[1] + sred[2] + sred[3];
        sred[4] = sred[4] + sred[5] + sred[6] + sred[7];
    }
    __syncthreads();
    a = sred[0];
    b = sred[4];
    __syncthreads();   // protect sred before next call reuses it
}

// ---------------- K2: x1 = LN(x + x@M^T + c), 8 rows per block -------------
#define ROWS_PER_BLK 8
__global__ void attn_ln1(const float* __restrict__ ln1_g,
                         const float* __restrict__ ln1_b) {
    __shared__ float sMt[DIM * DIM];    // Mt[j*DIM + i] = M[i][j]
    __shared__ float sx[DIM];
    __shared__ float sred[8];
    int t = threadIdx.x;
    for (int idx = t; idx < DIM * DIM; idx += blockDim.x) {
        int i = idx % DIM, j = idx / DIM;
        sMt[idx] = g_M[i * DIM + j];
    }
    int b0 = blockIdx.x * ROWS_PER_BLK;
    for (int r = 0; r < ROWS_PER_BLK; r++) {
        int b = b0 + r;
        __syncthreads();
        if (t < DIM) sx[t] = g_x[b * DIM + t];
        __syncthreads();
        float y = 0.f;
        if (t < DIM) {
            float acc = g_c[t];
            #pragma unroll 4
            for (int j = 0; j < DIM; j++)
                acc += sx[j] * sMt[j * DIM + t];
            y = sx[t] + acc;
        }
        float s = y, sq = y * y;
        block_reduce2(s, sq, sred);
        float m   = s / DIM;
        float var = sq / DIM - m * m;
        float inv = rsqrtf(var + EPS);
        if (t < DIM)
            g_x1[b * DIM + t] = (y - m) * inv * ln1_g[t] + ln1_b[t];
    }
}

// ---------------- K3/K4: tiled fp32 GEMM, C = act(A @ B^T + bias) ----------
// A: [M x K] row-major, B: [N x K] row-major, C: [M x N]
#define BM 64
#define BN 128
#define KT 32
#define AS_STRIDE (BM + 4)    // 68, keeps float4 alignment (68*4 % 16 == 0)
#define BS_STRIDE (BN + 4)    // 132

template<bool RELU>
__global__ __launch_bounds__(256)
void gemm_bias(const float* __restrict__ A, const float* __restrict__ Bm,
               const float* __restrict__ bias, float* __restrict__ C,
               int M, int N, int K) {
    __shared__ __align__(16) float As[KT * AS_STRIDE];
    __shared__ __align__(16) float Bs[KT * BS_STRIDE];
    int tid = threadIdx.x;
    int tx = tid & 31;     // 32 groups x 4 cols = 128 (n)
    int ty = tid >> 5;     // 8 groups x 8 rows  = 64  (m)
    int m0 = blockIdx.x * BM;
    int n0 = blockIdx.y * BN;

    float acc[8][4] = {};

    for (int k0 = 0; k0 < K; k0 += KT) {
        // load A tile (BM x KT), transpose into As[k][m]
        #pragma unroll
        for (int i = 0; i < (BM * KT) / 256; i++) {
            int idx = tid + i * 256;
            int k = idx & (KT - 1);
            int m = idx >> 5;
            float v = 0.f;
            if (k0 + k < K) v = A[(size_t)(m0 + m) * K + k0 + k];
            As[k * AS_STRIDE + m] = v;
        }
        // load B tile (BN x KT), transpose into Bs[k][n]
        #pragma unroll
        for (int i = 0; i < (BN * KT) / 256; i++) {
            int idx = tid + i * 256;
            int k = idx & (KT - 1);
            int n = idx >> 5;
            float v = 0.f;
            if ((n0 + n) < N && (k0 + k) < K)
                v = Bm[(size_t)(n0 + n) * K + k0 + k];
            Bs[k * BS_STRIDE + n] = v;
        }
        __syncthreads();

        #pragma unroll
        for (int k = 0; k < KT; k++) {
            float4 a0 = *(const float4*)&As[k * AS_STRIDE + ty * 8];
            float4 a1 = *(const float4*)&As[k * AS_STRIDE + ty * 8 + 4];
            float4 bb = *(const float4*)&Bs[k * BS_STRIDE + tx * 4];
            float am[8] = {a0.x, a0.y, a0.z, a0.w, a1.x, a1.y, a1.z, a1.w};
            float bn[4] = {bb.x, bb.y, bb.z, bb.w};
            #pragma unroll
            for (int i = 0; i < 8; i++)
                #pragma unroll
                for (int j = 0; j < 4; j++)
                    acc[i][j] += am[i] * bn[j];
        }
        __syncthreads();
    }

    #pragma unroll
    for (int i = 0; i < 8; i++) {
        int m = m0 + ty * 8 + i;
        #pragma unroll
        for (int j = 0; j < 4; j++) {
            int n = n0 + tx * 4 + j;
            if (n < N) {
                float v = acc[i][j] + bias[n];
                if (RELU) v = fmaxf(v, 0.f);
                C[(size_t)m * N + n] = v;
            }
        }
    }
}

// ---------------- K5: seq = LN(x1 + ff); res = b + rec . seq ---------------
__global__ void ln2_score(const float* __restrict__ ln2_g,
                          const float* __restrict__ ln2_b,
                          const int* __restrict__ items,
                          const float* __restrict__ rec_emb,
                          const float* __restrict__ rec_b,
                          float* __restrict__ out) {
    int b = blockIdx.x;
    __shared__ float sseq[DIM];
    __shared__ float sred[8];
    int t = threadIdx.x;

    float y = 0.f;
    if (t < DIM) y = g_x1[b * DIM + t] + g_ff[b * DIM + t];
    float s = y, sq = y * y;
    block_reduce2(s, sq, sred);
    float m   = s / DIM;
    float var = sq / DIM - m * m;
    float inv = rsqrtf(var + EPS);
    if (t < DIM) sseq[t] = (y - m) * inv * ln2_g[t] + ln2_b[t];
    __syncthreads();

    int w = t >> 5, lane = t & 31;
    for (int k = w; k < KPRED; k += 4) {
        int idx = items[b * KPRED + k];
        const float* r = rec_emb + (size_t)idx * DIM;
        float acc = 0.f;
        #pragma unroll
        for (int j = lane; j < DIM; j += 32)
            acc += r[j] * sseq[j];
        #pragma unroll
        for (int off = 16; off; off >>= 1)
            acc += __shfl_down_sync(0xffffffffu, acc, off);
        if (lane == 0)
            out[(size_t)b * KPRED + k] = acc + rec_b[idx];
    }
}

// ---------------- launch ----------------------------------------------------
extern "C" void kernel_launch(void* const* d_in, const int* in_sizes, int n_in,
                              void* d_out, int out_size) {
    const int*   item_seq    = (const int*)  d_in[0];
    const int*   items_pred  = (const int*)  d_in[1];
    const float* item_emb_w  = (const float*)d_in[2];
    const float* rec_emb_w   = (const float*)d_in[3];
    const float* rec_b_w     = (const float*)d_in[4];
    const float* in_proj_w   = (const float*)d_in[5];
    const float* in_proj_b   = (const float*)d_in[6];
    const float* out_proj_w  = (const float*)d_in[7];
    const float* out_proj_b  = (const float*)d_in[8];
    const float* ln1_g       = (const float*)d_in[9];
    const float* ln1_b       = (const float*)d_in[10];
    const float* ln2_g       = (const float*)d_in[11];
    const float* ln2_b       = (const float*)d_in[12];
    const float* ffn_w1      = (const float*)d_in[13];
    const float* ffn_b1      = (const float*)d_in[14];
    const float* ffn_w2      = (const float*)d_in[15];
    const float* ffn_b2      = (const float*)d_in[16];
    float* out = (float*)d_out;

    int B = in_sizes[0] / SEQ_L;

    float *p_x1, *p_h, *p_ff;
    cudaGetSymbolAddress((void**)&p_x1, g_x1);
    cudaGetSymbolAddress((void**)&p_h,  g_h);
    cudaGetSymbolAddress((void**)&p_ff, g_ff);

    precompute_attn<<<DIM, 128>>>(in_proj_w, in_proj_b, out_proj_w, out_proj_b);
    embed_sum<<<B, 128>>>(item_seq, item_emb_w);
    attn_ln1<<<B / ROWS_PER_BLK, 128>>>(ln1_g, ln1_b);
    gemm_bias<true ><<<dim3(B / BM, FFDIM / BN), 256>>>(p_x1, ffn_w1, ffn_b1, p_h,  B, FFDIM, DIM);
    gemm_bias<false><<<dim3(B / BM, 1),          256>>>(p_h,  ffn_w2, ffn_b2, p_ff, B, DIM, FFDIM);
    ln2_score<<<B, 128>>>(ln2_g, ln2_b, items_pred, rec_emb_w, rec_b_w, out);
}

// round 3
// speedup vs baseline: 1.7644x; 1.7644x over previous
#include <cuda_runtime.h>
#include <cuda_bf16.h>
#include <cstdint>

#define SEQ_L 50
#define DIM 100
#define KPAD 128
#define FFDIM 2048
#define KPRED 100
#define EPS 1e-5f
#define BMAX 16384

typedef __nv_bfloat16 bf16;

// ---------------- scratch (device globals) ---------------------------------
__device__ float g_x [BMAX * DIM];
__device__ float g_ff[BMAX * DIM];
__device__ float g_M [DIM * DIM];
__device__ float g_c [DIM];
__device__ bf16  g_x1h[BMAX * KPAD],  g_x1l[BMAX * KPAD];     // LN1 out, split planes
__device__ bf16  g_w1h[FFDIM * KPAD], g_w1l[FFDIM * KPAD];    // W1 [2048][128]
__device__ bf16  g_hh [(size_t)BMAX * FFDIM], g_hl[(size_t)BMAX * FFDIM]; // hidden
__device__ bf16  g_w2h[KPAD * FFDIM], g_w2l[KPAD * FFDIM];    // W2 [128][2048]

// ---------------- helpers ----------------------------------------------------
__device__ __forceinline__ uint32_t smem_u32(const void* p) {
    uint32_t a;
    asm("{ .reg .u64 t; cvta.to.shared.u64 t, %1; cvt.u32.u64 %0, t; }" : "=r"(a) : "l"(p));
    return a;
}
__device__ __forceinline__ void ldsm_x4(uint32_t addr, uint32_t& r0, uint32_t& r1,
                                        uint32_t& r2, uint32_t& r3) {
    asm volatile("ldmatrix.sync.aligned.m8n8.x4.shared.b16 {%0,%1,%2,%3}, [%4];"
                 : "=r"(r0), "=r"(r1), "=r"(r2), "=r"(r3) : "r"(addr));
}
__device__ __forceinline__ void mma_bf16(float* d, const uint32_t* a, const uint32_t* b) {
    asm volatile("mma.sync.aligned.m16n8k16.row.col.f32.bf16.bf16.f32 "
                 "{%0,%1,%2,%3}, {%4,%5,%6,%7}, {%8,%9}, {%0,%1,%2,%3};"
                 : "+f"(d[0]), "+f"(d[1]), "+f"(d[2]), "+f"(d[3])
                 : "r"(a[0]), "r"(a[1]), "r"(a[2]), "r"(a[3]), "r"(b[0]), "r"(b[1]));
}
__device__ __forceinline__ void cp16(uint32_t saddr, const void* g) {
    asm volatile("cp.async.cg.shared.global [%0], [%1], 16;" :: "r"(saddr), "l"(g));
}
#define CP_COMMIT() asm volatile("cp.async.commit_group;" ::: "memory")
template<int N> __device__ __forceinline__ void cp_wait() {
    asm volatile("cp.async.wait_group %0;" :: "n"(N) : "memory");
}
__device__ __forceinline__ void split2(float v, bf16& h, bf16& l) {
    h = __float2bfloat16(v);
    l = __float2bfloat16(v - __bfloat162float(h));
}

// ---------------- K0: collapse attention to one matrix ---------------------
__global__ void precompute_attn(const float* __restrict__ in_proj_w,
                                const float* __restrict__ in_proj_b,
                                const float* __restrict__ out_proj_w,
                                const float* __restrict__ out_proj_b) {
    int i = blockIdx.x, j = threadIdx.x;
    const float* Wv = in_proj_w + 2 * DIM * DIM;
    const float* bv = in_proj_b + 2 * DIM;
    if (j < DIM) {
        float s = 0.f;
        #pragma unroll 4
        for (int k = 0; k < DIM; k++)
            s += out_proj_w[i * DIM + k] * Wv[k * DIM + j];
        g_M[i * DIM + j] = s;
    }
    if (j == 0) {
        float s = out_proj_b[i];
        for (int k = 0; k < DIM; k++)
            s += out_proj_w[i * DIM + k] * bv[k];
        g_c[i] = s;
    }
}

// ---------------- K0b: weight split preconversion ---------------------------
__global__ void pre_w1(const float* __restrict__ w1) {
    int idx = blockIdx.x * 256 + threadIdx.x;        // FFDIM*KPAD
    if (idx >= FFDIM * KPAD) return;
    int n = idx >> 7, k = idx & 127;
    float v = (k < DIM) ? w1[n * DIM + k] : 0.f;
    split2(v, g_w1h[idx], g_w1l[idx]);
}
__global__ void pre_w2(const float* __restrict__ w2) {
    int idx = blockIdx.x * 256 + threadIdx.x;        // KPAD*FFDIM
    if (idx >= KPAD * FFDIM) return;
    int n = idx >> 11, k = idx & 2047;
    float v = (n < DIM) ? w2[n * FFDIM + k] : 0.f;
    split2(v, g_w2h[idx], g_w2l[idx]);
}

// ---------------- K1: embedding gather-sum ----------------------------------
__global__ void embed_sum(const int* __restrict__ seq,
                          const float* __restrict__ emb) {
    int b = blockIdx.x;
    __shared__ int s_idx[SEQ_L];
    int t = threadIdx.x;
    if (t < SEQ_L) s_idx[t] = seq[b * SEQ_L + t];
    __syncthreads();
    if (t < DIM) {
        float acc = 0.f;
        #pragma unroll 5
        for (int l = 0; l < SEQ_L; l++)
            acc += emb[(size_t)s_idx[l] * DIM + t];
        g_x[b * DIM + t] = acc;
    }
}

// ---------------- block reduce --------------------------------------------
__device__ __forceinline__ void block_reduce2(float& a, float& b, float* sred) {
    #pragma unroll
    for (int off = 16; off; off >>= 1) {
        a += __shfl_down_sync(0xffffffffu, a, off);
        b += __shfl_down_sync(0xffffffffu, b, off);
    }
    int w = threadIdx.x >> 5, lane = threadIdx.x & 31;
    if (lane == 0) { sred[w] = a; sred[w + 4] = b; }
    __syncthreads();
    if (threadIdx.x == 0) {
        sred[0] = sred[0] + sred[1] + sred[2] + sred[3];
        sred[4] = sred[4] + sred[5] + sred[6] + sred[7];
    }
    __syncthreads();
    a = sred[0];
    b = sred[4];
    __syncthreads();
}

// ---------------- K2: x1 = LN(x + x@M^T + c) -> split planes -----------------
#define ROWS_PER_BLK 32
__global__ void attn_ln1(const float* __restrict__ ln1_g,
                         const float* __restrict__ ln1_b) {
    __shared__ float sMt[DIM * DIM];
    __shared__ float sx[DIM];
    __shared__ float sred[8];
    int t = threadIdx.x;
    for (int idx = t; idx < DIM * DIM; idx += 128) {
        int i = idx % DIM, j = idx / DIM;
        sMt[idx] = g_M[i * DIM + j];
    }
    int b0 = blockIdx.x * ROWS_PER_BLK;
    for (int r = 0; r < ROWS_PER_BLK; r++) {
        int b = b0 + r;
        __syncthreads();
        if (t < DIM) sx[t] = g_x[b * DIM + t];
        __syncthreads();
        float y = 0.f;
        if (t < DIM) {
            float acc = g_c[t];
            #pragma unroll 4
            for (int j = 0; j < DIM; j++)
                acc += sx[j] * sMt[j * DIM + t];
            y = sx[t] + acc;
        }
        float s = y, sq = y * y;
        block_reduce2(s, sq, sred);
        float m   = s / DIM;
        float var = sq / DIM - m * m;
        float inv = rsqrtf(var + EPS);
        float outv = (t < DIM) ? (y - m) * inv * ln1_g[t] + ln1_b[t] : 0.f;
        split2(outv, g_x1h[b * KPAD + t], g_x1l[b * KPAD + t]);
    }
}

// ---------------- K3: GEMM1 mma.sync: h = relu(x1 @ W1^T + b1) ---------------
#define AS1 136
#define S1_AH 0
#define S1_AL (128 * AS1 * 2)
#define S1_BH (2 * 128 * AS1 * 2)
#define S1_BL (3 * 128 * AS1 * 2)
#define S1_BIAS (4 * 128 * AS1 * 2)
#define G1_SMEM (4 * 128 * AS1 * 2 + 512)

__global__ __launch_bounds__(256, 1)
void gemm1_mma(const float* __restrict__ b1) {
    extern __shared__ char smem[];
    uint32_t sb = smem_u32(smem);
    int tid = threadIdx.x, wid = tid >> 5, lid = tid & 31;
    int m0 = blockIdx.x * 128, n0 = blockIdx.y * 128;
    float* bias = (float*)(smem + S1_BIAS);
    if (tid < 128) bias[tid] = b1[n0 + tid];

    const uint4* Ah = (const uint4*)g_x1h + (size_t)m0 * 16;
    const uint4* Al = (const uint4*)g_x1l + (size_t)m0 * 16;
    const uint4* Bh = (const uint4*)g_w1h + (size_t)n0 * 16;
    const uint4* Bl = (const uint4*)g_w1l + (size_t)n0 * 16;
    #pragma unroll
    for (int i = 0; i < 8; i++) {
        int idx = tid + i * 256;
        int r = idx >> 4, c = idx & 15;
        uint32_t so = (uint32_t)((r * AS1 + c * 8) * 2);
        *(uint4*)(smem + S1_AH + so) = Ah[r * 16 + c];
        *(uint4*)(smem + S1_AL + so) = Al[r * 16 + c];
        *(uint4*)(smem + S1_BH + so) = Bh[r * 16 + c];
        *(uint4*)(smem + S1_BL + so) = Bl[r * 16 + c];
    }
    __syncthreads();

    int wm = wid >> 1, wn = wid & 1;
    int arow = wm * 32, brow = wn * 64;
    float acc[2][8][4] = {};
    int lr = lid & 15, lc8 = (lid >> 4) << 3;

    #pragma unroll
    for (int ks = 0; ks < 8; ks++) {
        int k0 = ks * 16;
        uint32_t ah[2][4], al[2][4];
        #pragma unroll
        for (int mi = 0; mi < 2; mi++) {
            uint32_t off = (uint32_t)(((arow + mi * 16 + lr) * AS1 + k0 + lc8) * 2);
            ldsm_x4(sb + S1_AH + off, ah[mi][0], ah[mi][1], ah[mi][2], ah[mi][3]);
            ldsm_x4(sb + S1_AL + off, al[mi][0], al[mi][1], al[mi][2], al[mi][3]);
        }
        uint32_t bh[8][2], bl[8][2];
        #pragma unroll
        for (int nj = 0; nj < 4; nj++) {
            uint32_t off = (uint32_t)(((brow + nj * 16 + lr) * AS1 + k0 + lc8) * 2);
            uint32_t r0, r1, r2, r3;
            ldsm_x4(sb + S1_BH + off, r0, r1, r2, r3);
            bh[nj * 2][0] = r0; bh[nj * 2 + 1][0] = r1;
            bh[nj * 2][1] = r2; bh[nj * 2 + 1][1] = r3;
            ldsm_x4(sb + S1_BL + off, r0, r1, r2, r3);
            bl[nj * 2][0] = r0; bl[nj * 2 + 1][0] = r1;
            bl[nj * 2][1] = r2; bl[nj * 2 + 1][1] = r3;
        }
        #pragma unroll
        for (int mi = 0; mi < 2; mi++)
            #pragma unroll
            for (int n = 0; n < 8; n++) {
                mma_bf16(acc[mi][n], ah[mi], bh[n]);
                mma_bf16(acc[mi][n], ah[mi], bl[n]);
                mma_bf16(acc[mi][n], al[mi], bh[n]);
            }
    }
    __syncthreads();

    // stage split planes into freed A smem, then coalesced store
    bf16* sh = (bf16*)(smem + S1_AH);
    bf16* sl = (bf16*)(smem + S1_AL);
    #pragma unroll
    for (int mi = 0; mi < 2; mi++)
        #pragma unroll
        for (int n = 0; n < 8; n++) {
            int r = arow + mi * 16 + (lid >> 2);
            int c = brow + n * 8 + (lid & 3) * 2;
            float v0 = fmaxf(acc[mi][n][0] + bias[c], 0.f);
            float v1 = fmaxf(acc[mi][n][1] + bias[c + 1], 0.f);
            float v2 = fmaxf(acc[mi][n][2] + bias[c], 0.f);
            float v3 = fmaxf(acc[mi][n][3] + bias[c + 1], 0.f);
            split2(v0, sh[r * AS1 + c],           sl[r * AS1 + c]);
            split2(v1, sh[r * AS1 + c + 1],       sl[r * AS1 + c + 1]);
            split2(v2, sh[(r + 8) * AS1 + c],     sl[(r + 8) * AS1 + c]);
            split2(v3, sh[(r + 8) * AS1 + c + 1], sl[(r + 8) * AS1 + c + 1]);
        }
    __syncthreads();
    uint4* HH = (uint4*)g_hh;
    uint4* HL = (uint4*)g_hl;
    #pragma unroll
    for (int i = 0; i < 8; i++) {
        int idx = tid + i * 256;
        int r = idx >> 4, c = idx & 15;
        uint32_t so = (uint32_t)((r * AS1 + c * 8) * 2);
        HH[(size_t)(m0 + r) * 256 + (n0 >> 3) + c] = *(uint4*)(smem + S1_AH + so);
        HL[(size_t)(m0 + r) * 256 + (n0 >> 3) + c] = *(uint4*)(smem + S1_AL + so);
    }
}

// ---------------- K4: GEMM2 mma.sync: ff = h @ W2^T + b2 ---------------------
#define AS2 72
#define ST_SZ (128 * AS2 * 2)          // 18432 per plane
#define BUF_SZ (4 * ST_SZ)             // 73728 per stage
#define S2_BIAS (2 * BUF_SZ)           // 147456
#define G2_SMEM (2 * BUF_SZ + 512)

__global__ __launch_bounds__(256, 1)
void gemm2_mma(const float* __restrict__ b2) {
    extern __shared__ char smem[];
    uint32_t sb = smem_u32(smem);
    int tid = threadIdx.x, wid = tid >> 5, lid = tid & 31;
    int m0 = blockIdx.x * 128;
    float* bias = (float*)(smem + S2_BIAS);
    if (tid < 128) bias[tid] = (tid < DIM) ? b2[tid] : 0.f;

    const uint4* srcAh = (const uint4*)g_hh + (size_t)m0 * 256;
    const uint4* srcAl = (const uint4*)g_hl + (size_t)m0 * 256;
    const uint4* srcBh = (const uint4*)g_w2h;
    const uint4* srcBl = (const uint4*)g_w2l;

    auto load_chunk = [&](int c, int buf) {
        uint32_t bb = sb + buf * BUF_SZ;
        #pragma unroll
        for (int i = 0; i < 4; i++) {
            int idx = tid + i * 256;
            int r = idx >> 3, cc = idx & 7;
            uint32_t so = (uint32_t)((r * AS2 + cc * 8) * 2);
            size_t go = (size_t)r * 256 + c * 8 + cc;
            cp16(bb + 0 * ST_SZ + so, srcAh + go);
            cp16(bb + 1 * ST_SZ + so, srcAl + go);
            cp16(bb + 2 * ST_SZ + so, srcBh + go);
            cp16(bb + 3 * ST_SZ + so, srcBl + go);
        }
    };

    int wm = wid >> 1, wn = wid & 1;
    int arow = wm * 32, brow = wn * 64;
    int lr = lid & 15, lc8 = (lid >> 4) << 3;
    float acc[2][8][4] = {};

    load_chunk(0, 0);
    CP_COMMIT();

    for (int c = 0; c < 32; c++) {
        if (c + 1 < 32) {
            load_chunk(c + 1, (c + 1) & 1);
            CP_COMMIT();
            cp_wait<1>();
        } else {
            cp_wait<0>();
        }
        __syncthreads();
        uint32_t bb = sb + (c & 1) * BUF_SZ;
        #pragma unroll
        for (int ks = 0; ks < 4; ks++) {
            int k0 = ks * 16;
            uint32_t ah[2][4], al[2][4];
            #pragma unroll
            for (int mi = 0; mi < 2; mi++) {
                uint32_t off = (uint32_t)(((arow + mi * 16 + lr) * AS2 + k0 + lc8) * 2);
                ldsm_x4(bb + 0 * ST_SZ + off, ah[mi][0], ah[mi][1], ah[mi][2], ah[mi][3]);
                ldsm_x4(bb + 1 * ST_SZ + off, al[mi][0], al[mi][1], al[mi][2], al[mi][3]);
            }
            uint32_t bh[8][2], bl[8][2];
            #pragma unroll
            for (int nj = 0; nj < 4; nj++) {
                uint32_t off = (uint32_t)(((brow + nj * 16 + lr) * AS2 + k0 + lc8) * 2);
                uint32_t r0, r1, r2, r3;
                ldsm_x4(bb + 2 * ST_SZ + off, r0, r1, r2, r3);
                bh[nj * 2][0] = r0; bh[nj * 2 + 1][0] = r1;
                bh[nj * 2][1] = r2; bh[nj * 2 + 1][1] = r3;
                ldsm_x4(bb + 3 * ST_SZ + off, r0, r1, r2, r3);
                bl[nj * 2][0] = r0; bl[nj * 2 + 1][0] = r1;
                bl[nj * 2][1] = r2; bl[nj * 2 + 1][1] = r3;
            }
            #pragma unroll
            for (int mi = 0; mi < 2; mi++)
                #pragma unroll
                for (int n = 0; n < 8; n++) {
                    mma_bf16(acc[mi][n], ah[mi], bh[n]);
                    mma_bf16(acc[mi][n], ah[mi], bl[n]);
                    mma_bf16(acc[mi][n], al[mi], bh[n]);
                }
        }
        __syncthreads();
    }

    #pragma unroll
    for (int mi = 0; mi < 2; mi++)
        #pragma unroll
        for (int n = 0; n < 8; n++) {
            int gr = m0 + arow + mi * 16 + (lid >> 2);
            int cc = brow + n * 8 + (lid & 3) * 2;
            if (cc < DIM) {
                g_ff[(size_t)gr * DIM + cc]       = acc[mi][n][0] + bias[cc];
                g_ff[(size_t)(gr + 8) * DIM + cc] = acc[mi][n][2] + bias[cc];
            }
            if (cc + 1 < DIM) {
                g_ff[(size_t)gr * DIM + cc + 1]       = acc[mi][n][1] + bias[cc + 1];
                g_ff[(size_t)(gr + 8) * DIM + cc + 1] = acc[mi][n][3] + bias[cc + 1];
            }
        }
}

// ---------------- K5: seq = LN(x1 + ff); res = b + rec . seq -----------------
__global__ void ln2_score(const float* __restrict__ ln2_g,
                          const float* __restrict__ ln2_b,
                          const int* __restrict__ items,
                          const float* __restrict__ rec_emb,
                          const float* __restrict__ rec_b,
                          float* __restrict__ out) {
    int b = blockIdx.x;
    __shared__ float sseq[DIM];
    __shared__ float sred[8];
    int t = threadIdx.x;

    float y = 0.f;
    if (t < DIM)
        y = __bfloat162float(g_x1h[b * KPAD + t]) + __bfloat162float(g_x1l[b * KPAD + t])
          + g_ff[b * DIM + t];
    float s = y, sq = y * y;
    block_reduce2(s, sq, sred);
    float m   = s / DIM;
    float var = sq / DIM - m * m;
    float inv = rsqrtf(var + EPS);
    if (t < DIM) sseq[t] = (y - m) * inv * ln2_g[t] + ln2_b[t];
    __syncthreads();

    int w = t >> 5, lane = t & 31;
    for (int k = w; k < KPRED; k += 4) {
        int idx = items[b * KPRED + k];
        const float* r = rec_emb + (size_t)idx * DIM;
        float acc = 0.f;
        #pragma unroll
        for (int j = lane; j < DIM; j += 32)
            acc += r[j] * sseq[j];
        #pragma unroll
        for (int off = 16; off; off >>= 1)
            acc += __shfl_down_sync(0xffffffffu, acc, off);
        if (lane == 0)
            out[(size_t)b * KPRED + k] = acc + rec_b[idx];
    }
}

// ---------------- launch ------------------------------------------------------
extern "C" void kernel_launch(void* const* d_in, const int* in_sizes, int n_in,
                              void* d_out, int out_size) {
    const int*   item_seq   = (const int*)  d_in[0];
    const int*   items_pred = (const int*)  d_in[1];
    const float* item_emb_w = (const float*)d_in[2];
    const float* rec_emb_w  = (const float*)d_in[3];
    const float* rec_b_w    = (const float*)d_in[4];
    const float* in_proj_w  = (const float*)d_in[5];
    const float* in_proj_b  = (const float*)d_in[6];
    const float* out_proj_w = (const float*)d_in[7];
    const float* out_proj_b = (const float*)d_in[8];
    const float* ln1_g      = (const float*)d_in[9];
    const float* ln1_b      = (const float*)d_in[10];
    const float* ln2_g      = (const float*)d_in[11];
    const float* ln2_b      = (const float*)d_in[12];
    const float* ffn_w1     = (const float*)d_in[13];
    const float* ffn_b1     = (const float*)d_in[14];
    const float* ffn_w2     = (const float*)d_in[15];
    const float* ffn_b2     = (const float*)d_in[16];
    float* out = (float*)d_out;

    int B = in_sizes[0] / SEQ_L;

    cudaFuncSetAttribute(gemm1_mma, cudaFuncAttributeMaxDynamicSharedMemorySize, G1_SMEM);
    cudaFuncSetAttribute(gemm2_mma, cudaFuncAttributeMaxDynamicSharedMemorySize, G2_SMEM);

    precompute_attn<<<DIM, 128>>>(in_proj_w, in_proj_b, out_proj_w, out_proj_b);
    pre_w1<<<(FFDIM * KPAD + 255) / 256, 256>>>(ffn_w1);
    pre_w2<<<(KPAD * FFDIM + 255) / 256, 256>>>(ffn_w2);
    embed_sum<<<B, 128>>>(item_seq, item_emb_w);
    attn_ln1<<<B / ROWS_PER_BLK, 128>>>(ln1_g, ln1_b);
    gemm1_mma<<<dim3(B / 128, FFDIM / 128), 256, G1_SMEM>>>(ffn_b1);
    gemm2_mma<<<B / 128, 256, G2_SMEM>>>(ffn_b2);
    ln2_score<<<B, 128>>>(ln2_g, ln2_b, items_pred, rec_emb_w, rec_b_w, out);
}

// round 4
// speedup vs baseline: 2.2780x; 1.2911x over previous
#include <cuda_runtime.h>
#include <cuda_bf16.h>
#include <cstdint>

#define SEQ_L 50
#define DIM 100
#define KPAD 128
#define FFDIM 2048
#define KPRED 100
#define EPS 1e-5f
#define BMAX 16384

typedef __nv_bfloat16 bf16;

// ---------------- scratch (device globals) ---------------------------------
__device__ float g_x [BMAX * DIM];
__device__ float g_ff[BMAX * DIM];
__device__ float g_c [KPAD];                                   // Wo@bv + bo, padded
__device__ bf16  g_Mh [KPAD * KPAD],  g_Ml [KPAD * KPAD];      // (Wo@Wv) split, padded
__device__ bf16  g_rech[KPAD * KPAD], g_recl[KPAD * KPAD];     // rec_emb split, padded
__device__ bf16  g_x1h[BMAX * KPAD],  g_x1l[BMAX * KPAD];
__device__ bf16  g_w1h[FFDIM * KPAD], g_w1l[FFDIM * KPAD];
__device__ bf16  g_hh [(size_t)BMAX * FFDIM], g_hl[(size_t)BMAX * FFDIM];
__device__ bf16  g_w2h[KPAD * FFDIM], g_w2l[KPAD * FFDIM];

// ---------------- helpers ----------------------------------------------------
__device__ __forceinline__ uint32_t smem_u32(const void* p) {
    uint32_t a;
    asm("{ .reg .u64 t; cvta.to.shared.u64 t, %1; cvt.u32.u64 %0, t; }" : "=r"(a) : "l"(p));
    return a;
}
__device__ __forceinline__ void ldsm_x4(uint32_t addr, uint32_t& r0, uint32_t& r1,
                                        uint32_t& r2, uint32_t& r3) {
    asm volatile("ldmatrix.sync.aligned.m8n8.x4.shared.b16 {%0,%1,%2,%3}, [%4];"
                 : "=r"(r0), "=r"(r1), "=r"(r2), "=r"(r3) : "r"(addr));
}
__device__ __forceinline__ void mma_bf16(float* d, const uint32_t* a, const uint32_t* b) {
    asm volatile("mma.sync.aligned.m16n8k16.row.col.f32.bf16.bf16.f32 "
                 "{%0,%1,%2,%3}, {%4,%5,%6,%7}, {%8,%9}, {%0,%1,%2,%3};"
                 : "+f"(d[0]), "+f"(d[1]), "+f"(d[2]), "+f"(d[3])
                 : "r"(a[0]), "r"(a[1]), "r"(a[2]), "r"(a[3]), "r"(b[0]), "r"(b[1]));
}
__device__ __forceinline__ void cp16(uint32_t saddr, const void* g) {
    asm volatile("cp.async.cg.shared.global [%0], [%1], 16;" :: "r"(saddr), "l"(g));
}
#define CP_COMMIT() asm volatile("cp.async.commit_group;" ::: "memory")
template<int N> __device__ __forceinline__ void cp_wait() {
    asm volatile("cp.async.wait_group %0;" :: "n"(N) : "memory");
}
__device__ __forceinline__ void split2(float v, bf16& h, bf16& l) {
    h = __float2bfloat16(v);
    l = __float2bfloat16(v - __bfloat162float(h));
}

// shared 128x128x128 split-bf16 MMA tile (stride 136 halfwords), acc += A@B^T x3
#define FAS 136
#define PL_SZ (128 * FAS * 2)        // 34816 B per plane
#define F_AH 0
#define F_AL PL_SZ
#define F_BH (2 * PL_SZ)
#define F_BL (3 * PL_SZ)
#define F_X  (4 * PL_SZ)             // 65536 B fp32 buffer
#define F_C  (4 * PL_SZ + 65536)     // 512 B vector
#define F_SMEM (F_C + 512)

__device__ __forceinline__ void mma_tile_128(uint32_t sb, float acc[2][8][4],
                                             int wid, int lid) {
    int wm = wid >> 1, wn = wid & 1;
    int arow = wm * 32, brow = wn * 64;
    int lr = lid & 15, lc8 = (lid >> 4) << 3;
    #pragma unroll
    for (int ks = 0; ks < 8; ks++) {
        int k0 = ks * 16;
        uint32_t ah[2][4], al[2][4];
        #pragma unroll
        for (int mi = 0; mi < 2; mi++) {
            uint32_t off = (uint32_t)(((arow + mi * 16 + lr) * FAS + k0 + lc8) * 2);
            ldsm_x4(sb + F_AH + off, ah[mi][0], ah[mi][1], ah[mi][2], ah[mi][3]);
            ldsm_x4(sb + F_AL + off, al[mi][0], al[mi][1], al[mi][2], al[mi][3]);
        }
        uint32_t bh[8][2], bl[8][2];
        #pragma unroll
        for (int nj = 0; nj < 4; nj++) {
            uint32_t off = (uint32_t)(((brow + nj * 16 + lr) * FAS + k0 + lc8) * 2);
            uint32_t r0, r1, r2, r3;
            ldsm_x4(sb + F_BH + off, r0, r1, r2, r3);
            bh[nj * 2][0] = r0; bh[nj * 2 + 1][0] = r1;
            bh[nj * 2][1] = r2; bh[nj * 2 + 1][1] = r3;
            ldsm_x4(sb + F_BL + off, r0, r1, r2, r3);
            bl[nj * 2][0] = r0; bl[nj * 2 + 1][0] = r1;
            bl[nj * 2][1] = r2; bl[nj * 2 + 1][1] = r3;
        }
        #pragma unroll
        for (int mi = 0; mi < 2; mi++)
            #pragma unroll
            for (int n = 0; n < 8; n++) {
                mma_bf16(acc[mi][n], ah[mi], bh[n]);
                mma_bf16(acc[mi][n], ah[mi], bl[n]);
                mma_bf16(acc[mi][n], al[mi], bh[n]);
            }
    }
}

// ---------------- K0: collapse attention + split ----------------------------
__global__ void precompute_attn(const float* __restrict__ in_proj_w,
                                const float* __restrict__ in_proj_b,
                                const float* __restrict__ out_proj_w,
                                const float* __restrict__ out_proj_b) {
    int i = blockIdx.x, j = threadIdx.x;   // grid 128, block 128
    const float* Wv = in_proj_w + 2 * DIM * DIM;
    const float* bv = in_proj_b + 2 * DIM;
    float mv = 0.f;
    if (i < DIM && j < DIM) {
        #pragma unroll 4
        for (int k = 0; k < DIM; k++)
            mv += out_proj_w[i * DIM + k] * Wv[k * DIM + j];
    }
    split2(mv, g_Mh[i * KPAD + j], g_Ml[i * KPAD + j]);
    if (j == 0) {
        float s = 0.f;
        if (i < DIM) {
            s = out_proj_b[i];
            for (int k = 0; k < DIM; k++)
                s += out_proj_w[i * DIM + k] * bv[k];
        }
        g_c[i] = s;
    }
}

__global__ void pre_rec(const float* __restrict__ rec_emb) {
    int idx = blockIdx.x * 256 + threadIdx.x;   // 128*128
    if (idx >= KPAD * KPAD) return;
    int n = idx >> 7, k = idx & 127;
    float v = (n < DIM && k < DIM) ? rec_emb[n * DIM + k] : 0.f;
    split2(v, g_rech[idx], g_recl[idx]);
}
__global__ void pre_w1(const float* __restrict__ w1) {
    int idx = blockIdx.x * 256 + threadIdx.x;
    if (idx >= FFDIM * KPAD) return;
    int n = idx >> 7, k = idx & 127;
    float v = (k < DIM) ? w1[n * DIM + k] : 0.f;
    split2(v, g_w1h[idx], g_w1l[idx]);
}
__global__ void pre_w2(const float* __restrict__ w2) {
    int idx = blockIdx.x * 256 + threadIdx.x;
    if (idx >= KPAD * FFDIM) return;
    int n = idx >> 11, k = idx & 2047;
    float v = (n < DIM) ? w2[n * FFDIM + k] : 0.f;
    split2(v, g_w2h[idx], g_w2l[idx]);
}

// ---------------- K1: embedding gather-sum ----------------------------------
__global__ void embed_sum(const int* __restrict__ seq,
                          const float* __restrict__ emb) {
    int b = blockIdx.x;
    __shared__ int s_idx[SEQ_L];
    int t = threadIdx.x;
    if (t < SEQ_L) s_idx[t] = seq[b * SEQ_L + t];
    __syncthreads();
    if (t < DIM) {
        float acc = 0.f;
        #pragma unroll 5
        for (int l = 0; l < SEQ_L; l++)
            acc += emb[(size_t)s_idx[l] * DIM + t];
        g_x[b * DIM + t] = acc;
    }
}

// ---------------- K2: fused attn + LN1 (tensor path) -------------------------
__global__ __launch_bounds__(256, 1)
void attn_ln1_tc(const float* __restrict__ ln1_g, const float* __restrict__ ln1_b) {
    extern __shared__ char smem[];
    uint32_t sb = smem_u32(smem);
    int tid = threadIdx.x, wid = tid >> 5, lid = tid & 31;
    int m0 = blockIdx.x * 128;
    float* xbuf = (float*)(smem + F_X);
    float* cvec = (float*)(smem + F_C);
    if (tid < KPAD) cvec[tid] = g_c[tid];

    // load x tile, split to A planes
    for (int idx = tid; idx < 128 * 128; idx += 256) {
        int r = idx >> 7, j = idx & 127;
        float v = (j < DIM) ? g_x[(size_t)(m0 + r) * DIM + j] : 0.f;
        xbuf[idx] = v;
        bf16 h, l; split2(v, h, l);
        *(bf16*)(smem + F_AH + ((r * FAS + j) << 1)) = h;
        *(bf16*)(smem + F_AL + ((r * FAS + j) << 1)) = l;
    }
    // load B planes (M split)
    const uint4* BH4 = (const uint4*)g_Mh;
    const uint4* BL4 = (const uint4*)g_Ml;
    #pragma unroll
    for (int i = 0; i < 8; i++) {
        int idx = tid + i * 256;
        int r = idx >> 4, c = idx & 15;
        uint32_t so = (uint32_t)((r * FAS + c * 8) * 2);
        *(uint4*)(smem + F_BH + so) = BH4[r * 16 + c];
        *(uint4*)(smem + F_BL + so) = BL4[r * 16 + c];
    }
    __syncthreads();

    float acc[2][8][4] = {};
    mma_tile_128(sb, acc, wid, lid);
    __syncthreads();

    // stage y = x + attn + c into fp32 buffer (reuse A-plane smem, stride 132)
    float* ybuf = (float*)(smem + F_AH);
    int wm = wid >> 1, wn = wid & 1;
    int arow = wm * 32, brow = wn * 64;
    #pragma unroll
    for (int mi = 0; mi < 2; mi++)
        #pragma unroll
        for (int n = 0; n < 8; n++) {
            int r = arow + mi * 16 + (lid >> 2);
            int c = brow + n * 8 + (lid & 3) * 2;
            ybuf[r * 132 + c]           = acc[mi][n][0] + xbuf[r * 128 + c]       + cvec[c];
            ybuf[r * 132 + c + 1]       = acc[mi][n][1] + xbuf[r * 128 + c + 1]   + cvec[c + 1];
            ybuf[(r + 8) * 132 + c]     = acc[mi][n][2] + xbuf[(r + 8) * 128 + c] + cvec[c];
            ybuf[(r + 8) * 132 + c + 1] = acc[mi][n][3] + xbuf[(r + 8) * 128 + c + 1] + cvec[c + 1];
        }
    __syncthreads();

    // LN per row (warp per row, 16 rows/warp), write split planes
    for (int rr = 0; rr < 16; rr++) {
        int r = wid * 16 + rr;
        float v[4], s = 0.f, sq = 0.f;
        #pragma unroll
        for (int q = 0; q < 4; q++) {
            int t = lid + q * 32;
            v[q] = (t < DIM) ? ybuf[r * 132 + t] : 0.f;
            s += v[q]; sq += v[q] * v[q];
        }
        #pragma unroll
        for (int off = 16; off; off >>= 1) {
            s  += __shfl_xor_sync(0xffffffffu, s,  off);
            sq += __shfl_xor_sync(0xffffffffu, sq, off);
        }
        float m = s / DIM;
        float inv = rsqrtf(sq / DIM - m * m + EPS);
        #pragma unroll
        for (int q = 0; q < 4; q++) {
            int t = lid + q * 32;
            float o = (t < DIM) ? (v[q] - m) * inv * ln1_g[t] + ln1_b[t] : 0.f;
            bf16 h, l; split2(o, h, l);
            g_x1h[(size_t)(m0 + r) * KPAD + t] = h;
            g_x1l[(size_t)(m0 + r) * KPAD + t] = l;
        }
    }
}

// ---------------- K3: GEMM1 mma.sync: h = relu(x1 @ W1^T + b1) ---------------
#define AS1 136
#define S1_AH 0
#define S1_AL (128 * AS1 * 2)
#define S1_BH (2 * 128 * AS1 * 2)
#define S1_BL (3 * 128 * AS1 * 2)
#define S1_BIAS (4 * 128 * AS1 * 2)
#define G1_SMEM (4 * 128 * AS1 * 2 + 512)

__global__ __launch_bounds__(256, 1)
void gemm1_mma(const float* __restrict__ b1) {
    extern __shared__ char smem[];
    uint32_t sb = smem_u32(smem);
    int tid = threadIdx.x, wid = tid >> 5, lid = tid & 31;
    int m0 = blockIdx.x * 128, n0 = blockIdx.y * 128;
    float* bias = (float*)(smem + S1_BIAS);
    if (tid < 128) bias[tid] = b1[n0 + tid];

    const uint4* Ah = (const uint4*)g_x1h + (size_t)m0 * 16;
    const uint4* Al = (const uint4*)g_x1l + (size_t)m0 * 16;
    const uint4* Bh = (const uint4*)g_w1h + (size_t)n0 * 16;
    const uint4* Bl = (const uint4*)g_w1l + (size_t)n0 * 16;
    #pragma unroll
    for (int i = 0; i < 8; i++) {
        int idx = tid + i * 256;
        int r = idx >> 4, c = idx & 15;
        uint32_t so = (uint32_t)((r * AS1 + c * 8) * 2);
        *(uint4*)(smem + S1_AH + so) = Ah[r * 16 + c];
        *(uint4*)(smem + S1_AL + so) = Al[r * 16 + c];
        *(uint4*)(smem + S1_BH + so) = Bh[r * 16 + c];
        *(uint4*)(smem + S1_BL + so) = Bl[r * 16 + c];
    }
    __syncthreads();

    float acc[2][8][4] = {};
    mma_tile_128(sb, acc, wid, lid);
    __syncthreads();

    int wm = wid >> 1, wn = wid & 1;
    int arow = wm * 32, brow = wn * 64;
    bf16* sh = (bf16*)(smem + S1_AH);
    bf16* sl = (bf16*)(smem + S1_AL);
    #pragma unroll
    for (int mi = 0; mi < 2; mi++)
        #pragma unroll
        for (int n = 0; n < 8; n++) {
            int r = arow + mi * 16 + (lid >> 2);
            int c = brow + n * 8 + (lid & 3) * 2;
            float v0 = fmaxf(acc[mi][n][0] + bias[c], 0.f);
            float v1 = fmaxf(acc[mi][n][1] + bias[c + 1], 0.f);
            float v2 = fmaxf(acc[mi][n][2] + bias[c], 0.f);
            float v3 = fmaxf(acc[mi][n][3] + bias[c + 1], 0.f);
            split2(v0, sh[r * AS1 + c],           sl[r * AS1 + c]);
            split2(v1, sh[r * AS1 + c + 1],       sl[r * AS1 + c + 1]);
            split2(v2, sh[(r + 8) * AS1 + c],     sl[(r + 8) * AS1 + c]);
            split2(v3, sh[(r + 8) * AS1 + c + 1], sl[(r + 8) * AS1 + c + 1]);
        }
    __syncthreads();
    uint4* HH = (uint4*)g_hh;
    uint4* HL = (uint4*)g_hl;
    #pragma unroll
    for (int i = 0; i < 8; i++) {
        int idx = tid + i * 256;
        int r = idx >> 4, c = idx & 15;
        uint32_t so = (uint32_t)((r * AS1 + c * 8) * 2);
        HH[(size_t)(m0 + r) * 256 + (n0 >> 3) + c] = *(uint4*)(smem + S1_AH + so);
        HL[(size_t)(m0 + r) * 256 + (n0 >> 3) + c] = *(uint4*)(smem + S1_AL + so);
    }
}

// ---------------- K4: GEMM2 mma.sync: ff = h @ W2^T + b2 ---------------------
#define AS2 72
#define ST_SZ (128 * AS2 * 2)
#define BUF_SZ (4 * ST_SZ)
#define S2_BIAS (2 * BUF_SZ)
#define G2_SMEM (2 * BUF_SZ + 512)

__global__ __launch_bounds__(256, 1)
void gemm2_mma(const float* __restrict__ b2) {
    extern __shared__ char smem[];
    uint32_t sb = smem_u32(smem);
    int tid = threadIdx.x, wid = tid >> 5, lid = tid & 31;
    int m0 = blockIdx.x * 128;
    float* bias = (float*)(smem + S2_BIAS);
    if (tid < 128) bias[tid] = (tid < DIM) ? b2[tid] : 0.f;

    const uint4* srcAh = (const uint4*)g_hh + (size_t)m0 * 256;
    const uint4* srcAl = (const uint4*)g_hl + (size_t)m0 * 256;
    const uint4* srcBh = (const uint4*)g_w2h;
    const uint4* srcBl = (const uint4*)g_w2l;

    auto load_chunk = [&](int c, int buf) {
        uint32_t bb = sb + buf * BUF_SZ;
        #pragma unroll
        for (int i = 0; i < 4; i++) {
            int idx = tid + i * 256;
            int r = idx >> 3, cc = idx & 7;
            uint32_t so = (uint32_t)((r * AS2 + cc * 8) * 2);
            size_t go = (size_t)r * 256 + c * 8 + cc;
            cp16(bb + 0 * ST_SZ + so, srcAh + go);
            cp16(bb + 1 * ST_SZ + so, srcAl + go);
            cp16(bb + 2 * ST_SZ + so, srcBh + go);
            cp16(bb + 3 * ST_SZ + so, srcBl + go);
        }
    };

    int wm = wid >> 1, wn = wid & 1;
    int arow = wm * 32, brow = wn * 64;
    int lr = lid & 15, lc8 = (lid >> 4) << 3;
    float acc[2][8][4] = {};

    load_chunk(0, 0);
    CP_COMMIT();

    for (int c = 0; c < 32; c++) {
        if (c + 1 < 32) {
            load_chunk(c + 1, (c + 1) & 1);
            CP_COMMIT();
            cp_wait<1>();
        } else {
            cp_wait<0>();
        }
        __syncthreads();
        uint32_t bb = sb + (c & 1) * BUF_SZ;
        #pragma unroll
        for (int ks = 0; ks < 4; ks++) {
            int k0 = ks * 16;
            uint32_t ah[2][4], al[2][4];
            #pragma unroll
            for (int mi = 0; mi < 2; mi++) {
                uint32_t off = (uint32_t)(((arow + mi * 16 + lr) * AS2 + k0 + lc8) * 2);
                ldsm_x4(bb + 0 * ST_SZ + off, ah[mi][0], ah[mi][1], ah[mi][2], ah[mi][3]);
                ldsm_x4(bb + 1 * ST_SZ + off, al[mi][0], al[mi][1], al[mi][2], al[mi][3]);
            }
            uint32_t bh[8][2], bl[8][2];
            #pragma unroll
            for (int nj = 0; nj < 4; nj++) {
                uint32_t off = (uint32_t)(((brow + nj * 16 + lr) * AS2 + k0 + lc8) * 2);
                uint32_t r0, r1, r2, r3;
                ldsm_x4(bb + 2 * ST_SZ + off, r0, r1, r2, r3);
                bh[nj * 2][0] = r0; bh[nj * 2 + 1][0] = r1;
                bh[nj * 2][1] = r2; bh[nj * 2 + 1][1] = r3;
                ldsm_x4(bb + 3 * ST_SZ + off, r0, r1, r2, r3);
                bl[nj * 2][0] = r0; bl[nj * 2 + 1][0] = r1;
                bl[nj * 2][1] = r2; bl[nj * 2 + 1][1] = r3;
            }
            #pragma unroll
            for (int mi = 0; mi < 2; mi++)
                #pragma unroll
                for (int n = 0; n < 8; n++) {
                    mma_bf16(acc[mi][n], ah[mi], bh[n]);
                    mma_bf16(acc[mi][n], ah[mi], bl[n]);
                    mma_bf16(acc[mi][n], al[mi], bh[n]);
                }
        }
        __syncthreads();
    }

    #pragma unroll
    for (int mi = 0; mi < 2; mi++)
        #pragma unroll
        for (int n = 0; n < 8; n++) {
            int gr = m0 + arow + mi * 16 + (lid >> 2);
            int cc = brow + n * 8 + (lid & 3) * 2;
            if (cc < DIM) {
                g_ff[(size_t)gr * DIM + cc]       = acc[mi][n][0] + bias[cc];
                g_ff[(size_t)(gr + 8) * DIM + cc] = acc[mi][n][2] + bias[cc];
            }
            if (cc + 1 < DIM) {
                g_ff[(size_t)gr * DIM + cc + 1]       = acc[mi][n][1] + bias[cc + 1];
                g_ff[(size_t)(gr + 8) * DIM + cc + 1] = acc[mi][n][3] + bias[cc + 1];
            }
        }
}

// ---------------- K5: fused LN2 + scoring (tensor path) ----------------------
__global__ __launch_bounds__(256, 1)
void ln2_score_tc(const float* __restrict__ ln2_g, const float* __restrict__ ln2_b,
                  const int* __restrict__ items, const float* __restrict__ rec_b,
                  float* __restrict__ out) {
    extern __shared__ char smem[];
    uint32_t sb = smem_u32(smem);
    int tid = threadIdx.x, wid = tid >> 5, lid = tid & 31;
    int m0 = blockIdx.x * 128;
    float* fbuf = (float*)(smem + F_X);     // fp32 scratch, stride 128
    float* srecb = (float*)(smem + F_C);
    if (tid < KPAD) srecb[tid] = (tid < DIM) ? rec_b[tid] : 0.f;

    // y = x1 + ff
    for (int idx = tid; idx < 128 * 128; idx += 256) {
        int r = idx >> 7, c = idx & 127;
        float v = 0.f;
        if (c < DIM)
            v = __bfloat162float(g_x1h[(size_t)(m0 + r) * KPAD + c])
              + __bfloat162float(g_x1l[(size_t)(m0 + r) * KPAD + c])
              + g_ff[(size_t)(m0 + r) * DIM + c];
        fbuf[idx] = v;
    }
    // load B planes (rec_emb split)
    const uint4* BH4 = (const uint4*)g_rech;
    const uint4* BL4 = (const uint4*)g_recl;
    #pragma unroll
    for (int i = 0; i < 8; i++) {
        int idx = tid + i * 256;
        int r = idx >> 4, c = idx & 15;
        uint32_t so = (uint32_t)((r * FAS + c * 8) * 2);
        *(uint4*)(smem + F_BH + so) = BH4[r * 16 + c];
        *(uint4*)(smem + F_BL + so) = BL4[r * 16 + c];
    }
    __syncthreads();

    // LN per row -> split planes in A smem
    for (int rr = 0; rr < 16; rr++) {
        int r = wid * 16 + rr;
        float v[4], s = 0.f, sq = 0.f;
        #pragma unroll
        for (int q = 0; q < 4; q++) {
            int t = lid + q * 32;
            v[q] = (t < DIM) ? fbuf[r * 128 + t] : 0.f;
            s += v[q]; sq += v[q] * v[q];
        }
        #pragma unroll
        for (int off = 16; off; off >>= 1) {
            s  += __shfl_xor_sync(0xffffffffu, s,  off);
            sq += __shfl_xor_sync(0xffffffffu, sq, off);
        }
        float m = s / DIM;
        float inv = rsqrtf(sq / DIM - m * m + EPS);
        #pragma unroll
        for (int q = 0; q < 4; q++) {
            int t = lid + q * 32;
            float o = (t < DIM) ? (v[q] - m) * inv * ln2_g[t] + ln2_b[t] : 0.f;
            bf16 h, l; split2(o, h, l);
            *(bf16*)(smem + F_AH + ((r * FAS + t) << 1)) = h;
            *(bf16*)(smem + F_AL + ((r * FAS + t) << 1)) = l;
        }
    }
    __syncthreads();

    float acc[2][8][4] = {};
    mma_tile_128(sb, acc, wid, lid);
    __syncthreads();

    // stage P into fp32 buffer (stride 128)
    int wm = wid >> 1, wn = wid & 1;
    int arow = wm * 32, brow = wn * 64;
    #pragma unroll
    for (int mi = 0; mi < 2; mi++)
        #pragma unroll
        for (int n = 0; n < 8; n++) {
            int r = arow + mi * 16 + (lid >> 2);
            int c = brow + n * 8 + (lid & 3) * 2;
            fbuf[r * 128 + c]           = acc[mi][n][0];
            fbuf[r * 128 + c + 1]       = acc[mi][n][1];
            fbuf[(r + 8) * 128 + c]     = acc[mi][n][2];
            fbuf[(r + 8) * 128 + c + 1] = acc[mi][n][3];
        }
    __syncthreads();

    // gather: out[b,k] = P[r][items[b,k]] + rec_b[idx]
    for (int o = tid; o < 128 * KPRED; o += 256) {
        int r = o / KPRED, k = o - r * KPRED;
        int idx = items[(size_t)(m0 + r) * KPRED + k];
        out[(size_t)(m0 + r) * KPRED + k] = fbuf[r * 128 + idx] + srecb[idx];
    }
}

// ---------------- launch ------------------------------------------------------
extern "C" void kernel_launch(void* const* d_in, const int* in_sizes, int n_in,
                              void* d_out, int out_size) {
    const int*   item_seq   = (const int*)  d_in[0];
    const int*   items_pred = (const int*)  d_in[1];
    const float* item_emb_w = (const float*)d_in[2];
    const float* rec_emb_w  = (const float*)d_in[3];
    const float* rec_b_w    = (const float*)d_in[4];
    const float* in_proj_w  = (const float*)d_in[5];
    const float* in_proj_b  = (const float*)d_in[6];
    const float* out_proj_w = (const float*)d_in[7];
    const float* out_proj_b = (const float*)d_in[8];
    const float* ln1_g      = (const float*)d_in[9];
    const float* ln1_b      = (const float*)d_in[10];
    const float* ln2_g      = (const float*)d_in[11];
    const float* ln2_b      = (const float*)d_in[12];
    const float* ffn_w1     = (const float*)d_in[13];
    const float* ffn_b1     = (const float*)d_in[14];
    const float* ffn_w2     = (const float*)d_in[15];
    const float* ffn_b2     = (const float*)d_in[16];
    float* out = (float*)d_out;

    int B = in_sizes[0] / SEQ_L;

    cudaFuncSetAttribute(attn_ln1_tc,  cudaFuncAttributeMaxDynamicSharedMemorySize, F_SMEM);
    cudaFuncSetAttribute(ln2_score_tc, cudaFuncAttributeMaxDynamicSharedMemorySize, F_SMEM);
    cudaFuncSetAttribute(gemm1_mma, cudaFuncAttributeMaxDynamicSharedMemorySize, G1_SMEM);
    cudaFuncSetAttribute(gemm2_mma, cudaFuncAttributeMaxDynamicSharedMemorySize, G2_SMEM);

    precompute_attn<<<KPAD, 128>>>(in_proj_w, in_proj_b, out_proj_w, out_proj_b);
    pre_rec<<<(KPAD * KPAD + 255) / 256, 256>>>(rec_emb_w);
    pre_w1<<<(FFDIM * KPAD + 255) / 256, 256>>>(ffn_w1);
    pre_w2<<<(KPAD * FFDIM + 255) / 256, 256>>>(ffn_w2);
    embed_sum<<<B, 128>>>(item_seq, item_emb_w);
    attn_ln1_tc<<<B / 128, 256, F_SMEM>>>(ln1_g, ln1_b);
    gemm1_mma<<<dim3(B / 128, FFDIM / 128), 256, G1_SMEM>>>(ffn_b1);
    gemm2_mma<<<B / 128, 256, G2_SMEM>>>(ffn_b2);
    ln2_score_tc<<<B / 128, 256, F_SMEM>>>(ln2_g, ln2_b, items_pred, rec_b_w, out);
}